// round 1
// baseline (speedup 1.0000x reference)
#include <cuda_runtime.h>

// Problem constants
#define Bn 4
#define Ln 2048
#define Dn 256
#define NG 3
#define SLOTS 64
#define ROWS 192          // SLOTS*NG
#define MPAD 260          // padded row stride (words) for conflict-free LDS.128
#define TILE 56           // positions per block (4 * 37 = 148 blocks = 1 wave)
#define CH 8              // positions per chunk
#define XR (CH + 2)       // x rows per chunk (2 history rows)
#define NTHREADS 192
#define TILES_PER_B 37    // ceil(2048/56)

// dynamic smem layout (floats):
//  mem_s : ROWS * MPAD            = 49920
//  xs    : XR * Dn                =  2560
//  gs    : XR * ROWS              =  1920
//  bias_s: ROWS                   =   192
//  best_s: CH * SLOTS ints        =   512 (words)
#define SMEM_FLOATS (ROWS*MPAD + XR*Dn + XR*ROWS + ROWS + CH*SLOTS)

__global__ void __launch_bounds__(NTHREADS, 1)
pnm_kernel(const float* __restrict__ x,
           const float* __restrict__ mem,
           const float* __restrict__ bias,
           float* __restrict__ out)
{
    extern __shared__ float smem[];
    float* mem_s  = smem;                       // [ROWS][MPAD]
    float* xs     = mem_s + ROWS * MPAD;        // [XR][Dn]
    float* gs     = xs + XR * Dn;               // [XR][ROWS]
    float* bias_s = gs + XR * ROWS;             // [ROWS]
    int*   best_s = (int*)(bias_s + ROWS);      // [CH][SLOTS]

    const int tid = threadIdx.x;
    const int b   = blockIdx.x / TILES_PER_B;
    const int l0  = (blockIdx.x % TILES_PER_B) * TILE;
    const int lend = (l0 + TILE < Ln) ? (l0 + TILE) : Ln;

    // ---- load memory (192 x 256 f32) into padded smem, float4 ----
    for (int i = tid; i < ROWS * (Dn / 4); i += NTHREADS) {
        int r = i / (Dn / 4);
        int c = i % (Dn / 4);
        float4 v = ((const float4*)mem)[r * (Dn / 4) + c];
        ((float4*)(mem_s + r * MPAD))[c] = v;
    }
    for (int i = tid; i < ROWS; i += NTHREADS) bias_s[i] = bias[i];
    __syncthreads();

    for (int c0 = l0; c0 < lend; c0 += CH) {
        const int npos = (CH < lend - c0) ? CH : (lend - c0);   // always 8 for these shapes
        const int nrows = npos + 2;

        // ---- load x rows l' = c0-2 .. c0+npos-1 (zeros for l' < 0) ----
        for (int i = tid; i < nrows * (Dn / 4); i += NTHREADS) {
            int r  = i / (Dn / 4);
            int cc = i % (Dn / 4);
            int lp = c0 - 2 + r;
            float4 v = make_float4(0.f, 0.f, 0.f, 0.f);
            if (lp >= 0)
                v = ((const float4*)x)[((size_t)b * Ln + lp) * (Dn / 4) + cc];
            ((float4*)(xs + r * Dn))[cc] = v;
        }
        __syncthreads();

        // ---- GEMM panel: gs[r][j] = dot(xs[r], mem_s[j]), j = tid (0..191) ----
        {
            const int j = tid;
            float acc[XR];
            #pragma unroll
            for (int r = 0; r < XR; r++) acc[r] = 0.f;

            const float4* mrow = (const float4*)(mem_s + j * MPAD);
            #pragma unroll 4
            for (int d4 = 0; d4 < Dn / 4; d4++) {
                float4 m4 = mrow[d4];
                #pragma unroll
                for (int r = 0; r < XR; r++) {
                    float4 x4 = ((const float4*)(xs + r * Dn))[d4];
                    acc[r] += m4.x * x4.x;
                    acc[r] += m4.y * x4.y;
                    acc[r] += m4.z * x4.z;
                    acc[r] += m4.w * x4.w;
                }
            }
            #pragma unroll
            for (int r = 0; r < XR; r++) gs[r * ROWS + j] = acc[r];
        }
        __syncthreads();

        // ---- argmax over n: score(m,n) = G[l-2+n][m,n] + bias[m,n] ----
        // position p (l = c0+p): n=0 -> gs row p, n=1 -> row p+1, n=2 -> row p+2
        for (int pm = tid; pm < npos * SLOTS; pm += NTHREADS) {
            int p = pm / SLOTS;
            int m = pm % SLOTS;
            float s0 = gs[(p + 0) * ROWS + m * 3 + 0] + bias_s[m * 3 + 0];
            float s1 = gs[(p + 1) * ROWS + m * 3 + 1] + bias_s[m * 3 + 1];
            float s2 = gs[(p + 2) * ROWS + m * 3 + 2] + bias_s[m * 3 + 2];
            int   bn = 0;
            float bv = s0;
            if (s1 > bv) { bv = s1; bn = 1; }
            if (s2 > bv) { bv = s2; bn = 2; }
            best_s[p * SLOTS + m] = m * 3 + bn;   // direct smem row index
        }
        __syncthreads();

        // ---- gather-sum: out[l][d] = sum_m mem_s[best[p][m]][d] ----
        for (int p = 0; p < npos; p++) {
            const int4* bp = (const int4*)(best_s + p * SLOTS);
            for (int d = tid; d < Dn; d += NTHREADS) {
                float acc = 0.f;
                #pragma unroll
                for (int m4 = 0; m4 < SLOTS / 4; m4++) {
                    int4 r4 = bp[m4];              // warp-uniform broadcast
                    acc += mem_s[r4.x * MPAD + d];
                    acc += mem_s[r4.y * MPAD + d];
                    acc += mem_s[r4.z * MPAD + d];
                    acc += mem_s[r4.w * MPAD + d];
                }
                out[((size_t)b * Ln + (c0 + p)) * Dn + d] = acc;
            }
        }
        __syncthreads();
    }
}

extern "C" void kernel_launch(void* const* d_in, const int* in_sizes, int n_in,
                              void* d_out, int out_size)
{
    const float* x    = (const float*)d_in[0];   // (4, 2048, 256) f32
    const float* mem  = (const float*)d_in[1];   // (64, 3, 256)   f32
    const float* bias = (const float*)d_in[2];   // (64, 3)        f32
    float* out        = (float*)d_out;           // (4, 2048, 256) f32

    (void)in_sizes; (void)n_in; (void)out_size;

    const int smem_bytes = SMEM_FLOATS * (int)sizeof(float);
    cudaFuncSetAttribute(pnm_kernel,
                         cudaFuncAttributeMaxDynamicSharedMemorySize,
                         smem_bytes);

    pnm_kernel<<<Bn * TILES_PER_B, NTHREADS, smem_bytes>>>(x, mem, bias, out);
}

// round 3
// speedup vs baseline: 1.3423x; 1.3423x over previous
#include <cuda_runtime.h>

// Problem constants
#define Bn 4
#define Ln 2048
#define Dn 256
#define SLOTS 64
#define ROWS 192          // SLOTS * 3
#define MPAD 260          // padded row stride (words): conflict-free LDS.128, 16B aligned
#define TILE 56           // 4 * 37 = 148 blocks = one full wave
#define CH 8              // positions per chunk
#define NT 384            // 12 warps
#define TILES_PER_B 37

// smem layout (in floats/words)
#define OFF_GS   (ROWS * MPAD)             // 49920 : gs[10][192] rolling G panel
#define OFF_PART (OFF_GS + 10 * ROWS)      // +1920 : part[3][8][192] split-K partials
#define OFF_BIAS (OFF_PART + 3 * 8 * ROWS) // +4608
#define OFF_BEST (OFF_BIAS + ROWS)         // +192  : best[8][64] (row*MPAD pre-mult)
#define SMEM_WORDS (OFF_BEST + CH * SLOTS) // +512 -> 57152 words = 228608 B

typedef unsigned long long u64;

__device__ __forceinline__ u64 fma2(u64 a, u64 b, u64 c) {
    u64 d;
    asm("fma.rn.f32x2 %0, %1, %2, %3;" : "=l"(d) : "l"(a), "l"(b), "l"(c));
    return d;
}
__device__ __forceinline__ u64 add2(u64 a, u64 b) {
    u64 d;
    asm("add.rn.f32x2 %0, %1, %2;" : "=l"(d) : "l"(a), "l"(b));
    return d;
}
__device__ __forceinline__ float hsum2(u64 a) {
    float lo, hi;
    asm("mov.b64 {%0,%1}, %2;" : "=f"(lo), "=f"(hi) : "l"(a));
    return lo + hi;
}

__global__ void __launch_bounds__(NT, 1)
pnm_kernel(const float* __restrict__ x,
           const float* __restrict__ mem,
           const float* __restrict__ bias,
           float* __restrict__ out)
{
    extern __shared__ float smem[];
    float* mem_s  = smem;                 // [ROWS][MPAD]
    float* gs     = smem + OFF_GS;        // [10][ROWS]
    float* part   = smem + OFF_PART;      // [3][8][ROWS]
    float* bias_s = smem + OFF_BIAS;      // [ROWS]
    int*   best_s = (int*)(smem + OFF_BEST); // [CH][SLOTS]

    const int tid = threadIdx.x;
    const int b   = blockIdx.x / TILES_PER_B;
    const int l0  = (blockIdx.x % TILES_PER_B) * TILE;
    const int lend = (l0 + TILE < Ln) ? (l0 + TILE) : Ln;

    // ---- stage memory (192 x 256 f32) into padded smem ----
    for (int i = tid; i < ROWS * (Dn / 4); i += NT) {
        int r = i >> 6, c = i & 63;
        float4 v = ((const float4*)mem)[i];
        ((float4*)(mem_s + r * MPAD))[c] = v;
    }
    if (tid < ROWS) bias_s[tid] = bias[tid];
    __syncthreads();

    // GEMM warp decomposition: 12 warps = 3 column-groups x 4 K-chunks
    const int warp = tid >> 5, lane = tid & 31;
    const int j0 = (warp % 3) * 64 + lane;   // first mem-row (column of G)
    const int j1 = j0 + 32;                  // second
    const int kc = warp / 3;                 // K-chunk: d4 in [kc*16, kc*16+16)

    const float* xb = x + (size_t)b * Ln * Dn;

    for (int c0 = l0; c0 < lend; c0 += CH) {
        // ---- roll / bootstrap gs rows 0,1 (logical l' = c0-2, c0-1) ----
        {
            int rI = tid / ROWS;       // 0 or 1 (NT == 2*ROWS)
            int j  = tid - rI * ROWS;
            if (c0 == l0) {
                int lp = l0 - 2 + rI;
                float v = 0.f;
                if (lp >= 0) {
                    const ulonglong2* mp = (const ulonglong2*)(mem_s + j * MPAD);
                    const ulonglong2* xp = (const ulonglong2*)(xb + (size_t)lp * Dn);
                    u64 a = 0;
                    #pragma unroll 4
                    for (int d4 = 0; d4 < 64; ++d4) {
                        ulonglong2 m  = mp[d4];
                        ulonglong2 xv = xp[d4];
                        a = fma2(m.x, xv.x, a);
                        a = fma2(m.y, xv.y, a);
                    }
                    v = hsum2(a);
                }
                gs[rI * ROWS + j] = v;
            } else {
                gs[rI * ROWS + j] = gs[(8 + rI) * ROWS + j];
            }
        }
        __syncthreads();   // roll-read of gs[8,9] must finish before kc0 rewrites them

        // ---- split-K GEMM: 8 new rows (l' = c0..c0+7), 2 cols/thread, f32x2 FMA ----
        u64 acc[8][2];
        #pragma unroll
        for (int r = 0; r < 8; r++) { acc[r][0] = 0ULL; acc[r][1] = 0ULL; }
        {
            const ulonglong2* mp0 = (const ulonglong2*)(mem_s + j0 * MPAD);
            const ulonglong2* mp1 = (const ulonglong2*)(mem_s + j1 * MPAD);
            const ulonglong2* xp  = (const ulonglong2*)(xb + (size_t)c0 * Dn);
            const int d4b = kc * 16;
            #pragma unroll 2
            for (int d4 = d4b; d4 < d4b + 16; ++d4) {
                ulonglong2 m0 = mp0[d4];
                ulonglong2 m1 = mp1[d4];
                #pragma unroll
                for (int r = 0; r < 8; r++) {
                    // x row stride = 256 floats = 64 ulonglong2 (R2 bug: was 32)
                    ulonglong2 xv = xp[r * 64 + d4];   // broadcast LDG.128 (L1/L2 hit)
                    acc[r][0] = fma2(m0.x, xv.x, acc[r][0]);
                    acc[r][0] = fma2(m0.y, xv.y, acc[r][0]);
                    acc[r][1] = fma2(m1.x, xv.x, acc[r][1]);
                    acc[r][1] = fma2(m1.y, xv.y, acc[r][1]);
                }
            }
        }
        if (kc == 0) {
            #pragma unroll
            for (int r = 0; r < 8; r++) {
                gs[(r + 2) * ROWS + j0] = hsum2(acc[r][0]);
                gs[(r + 2) * ROWS + j1] = hsum2(acc[r][1]);
            }
        } else {
            float* pp = part + (kc - 1) * (8 * ROWS);
            #pragma unroll
            for (int r = 0; r < 8; r++) {
                pp[r * ROWS + j0] = hsum2(acc[r][0]);
                pp[r * ROWS + j1] = hsum2(acc[r][1]);
            }
        }
        __syncthreads();

        // ---- K-partial combine ----
        for (int i = tid; i < 8 * ROWS; i += NT)
            gs[i + 2 * ROWS] += part[i] + part[8 * ROWS + i] + part[16 * ROWS + i];
        __syncthreads();

        // ---- argmax over n ----
        for (int pm = tid; pm < CH * SLOTS; pm += NT) {
            int p = pm >> 6;
            int m3 = (pm & 63) * 3;
            float s0 = gs[(p + 0) * ROWS + m3 + 0] + bias_s[m3 + 0];
            float s1 = gs[(p + 1) * ROWS + m3 + 1] + bias_s[m3 + 1];
            float s2 = gs[(p + 2) * ROWS + m3 + 2] + bias_s[m3 + 2];
            int   bn = 0;
            float bv = s0;
            if (s1 > bv) { bv = s1; bn = 1; }
            if (s2 > bv) { bv = s2; bn = 2; }
            best_s[pm] = (m3 + bn) * MPAD;   // pre-multiplied smem row offset
        }
        __syncthreads();

        // ---- gather-sum from smem: out[p][:] = sum_m mem_s[best] ----
        for (int it = tid; it < CH * (Dn / 4); it += NT) {
            int p = it >> 6, d4 = it & 63;
            const int4* bp = (const int4*)(best_s + p * SLOTS);
            u64 ax[4] = {0ULL, 0ULL, 0ULL, 0ULL};
            u64 ay[4] = {0ULL, 0ULL, 0ULL, 0ULL};
            #pragma unroll
            for (int m4 = 0; m4 < 16; m4++) {
                int4 r4 = bp[m4];               // warp-uniform broadcast
                int q = m4 & 3;
                ulonglong2 v;
                v = ((const ulonglong2*)(mem_s + r4.x))[d4];
                ax[q] = add2(ax[q], v.x); ay[q] = add2(ay[q], v.y);
                v = ((const ulonglong2*)(mem_s + r4.y))[d4];
                ax[q] = add2(ax[q], v.x); ay[q] = add2(ay[q], v.y);
                v = ((const ulonglong2*)(mem_s + r4.z))[d4];
                ax[q] = add2(ax[q], v.x); ay[q] = add2(ay[q], v.y);
                v = ((const ulonglong2*)(mem_s + r4.w))[d4];
                ax[q] = add2(ax[q], v.x); ay[q] = add2(ay[q], v.y);
            }
            u64 a0 = add2(add2(ax[0], ax[1]), add2(ax[2], ax[3]));
            u64 a1 = add2(add2(ay[0], ay[1]), add2(ay[2], ay[3]));
            float x0, x1, y0, y1;
            asm("mov.b64 {%0,%1}, %2;" : "=f"(x0), "=f"(x1) : "l"(a0));
            asm("mov.b64 {%0,%1}, %2;" : "=f"(y0), "=f"(y1) : "l"(a1));
            ((float4*)(out + ((size_t)b * Ln + c0 + p) * Dn))[d4] =
                make_float4(x0, x1, y0, y1);
        }
        // no trailing sync needed: the only later writer that conflicts with
        // this phase's reads (argmax -> best_s) is fenced by three barriers.
    }
}

extern "C" void kernel_launch(void* const* d_in, const int* in_sizes, int n_in,
                              void* d_out, int out_size)
{
    const float* x    = (const float*)d_in[0];   // (4, 2048, 256) f32
    const float* mem  = (const float*)d_in[1];   // (64, 3, 256)   f32
    const float* bias = (const float*)d_in[2];   // (64, 3)        f32
    float* out        = (float*)d_out;           // (4, 2048, 256) f32

    (void)in_sizes; (void)n_in; (void)out_size;

    const int smem_bytes = SMEM_WORDS * (int)sizeof(float);   // 228608
    cudaFuncSetAttribute(pnm_kernel,
                         cudaFuncAttributeMaxDynamicSharedMemorySize,
                         smem_bytes);

    pnm_kernel<<<Bn * TILES_PER_B, NT, smem_bytes>>>(x, mem, bias, out);
}

// round 4
// speedup vs baseline: 1.3647x; 1.0167x over previous
#include <cuda_runtime.h>

// Problem constants
#define Bn 4
#define Ln 2048
#define Dn 256
#define SLOTS 64
#define ROWS 192          // SLOTS * 3
#define MPAD 260          // padded stride (words): (MPAD/4)=65 odd -> conflict-free LDS.128
#define TILE 56           // 4 * 37 = 148 blocks = one full wave
#define CH 8              // positions per chunk
#define NT 384            // 12 warps
#define TILES_PER_B 37

// smem layout (words)
#define OFF_GSM  (ROWS * MPAD)                // 49920 : gsm[8][192]  kc0 partials
#define OFF_PART (OFF_GSM + CH * ROWS)        // +1536 : part[3][8][192] kc1..3 partials
#define OFF_HEAD (OFF_PART + 3 * CH * ROWS)   // +4608 : head[2][2][192] rolled G rows
#define OFF_BIAS (OFF_HEAD + 2 * 2 * ROWS)    // +768
#define OFF_BEST (OFF_BIAS + ROWS)            // +192  : best[8][64] (row*MPAD premult)
#define SMEM_WORDS (OFF_BEST + CH * SLOTS)    // +512 -> 57536 words = 230144 B

typedef unsigned long long u64;

__device__ __forceinline__ u64 fma2(u64 a, u64 b, u64 c) {
    u64 d;
    asm("fma.rn.f32x2 %0, %1, %2, %3;" : "=l"(d) : "l"(a), "l"(b), "l"(c));
    return d;
}
__device__ __forceinline__ u64 add2(u64 a, u64 b) {
    u64 d;
    asm("add.rn.f32x2 %0, %1, %2;" : "=l"(d) : "l"(a), "l"(b));
    return d;
}
__device__ __forceinline__ float hsum2(u64 a) {
    float lo, hi;
    asm("mov.b64 {%0,%1}, %2;" : "=f"(lo), "=f"(hi) : "l"(a));
    return lo + hi;
}

// split-K GEMM slice: this thread's 2 columns (j0,j1), 16 d4 K-chunk, 8 rows.
__device__ __forceinline__ void gemm_chunk(
    const float* __restrict__ xb, int c0,
    const ulonglong2* __restrict__ mp0, const ulonglong2* __restrict__ mp1,
    float* __restrict__ gdst, int d4b, int j0, int j1)
{
    const ulonglong2* xp = (const ulonglong2*)(xb + (size_t)c0 * Dn);
    u64 acc[8][2];
    #pragma unroll
    for (int r = 0; r < 8; r++) { acc[r][0] = 0ULL; acc[r][1] = 0ULL; }
    #pragma unroll 2
    for (int d4 = d4b; d4 < d4b + 16; ++d4) {
        ulonglong2 m0 = mp0[d4];
        ulonglong2 m1 = mp1[d4];
        #pragma unroll
        for (int r = 0; r < 8; r++) {
            ulonglong2 xv = xp[r * 64 + d4];     // broadcast LDG.128 (warp-uniform addr)
            acc[r][0] = fma2(m0.x, xv.x, acc[r][0]);
            acc[r][0] = fma2(m0.y, xv.y, acc[r][0]);
            acc[r][1] = fma2(m1.x, xv.x, acc[r][1]);
            acc[r][1] = fma2(m1.y, xv.y, acc[r][1]);
        }
    }
    #pragma unroll
    for (int r = 0; r < 8; r++) {
        gdst[r * ROWS + j0] = hsum2(acc[r][0]);
        gdst[r * ROWS + j1] = hsum2(acc[r][1]);
    }
}

__global__ void __launch_bounds__(NT, 1)
pnm_kernel(const float* __restrict__ x,
           const float* __restrict__ mem,
           const float* __restrict__ bias,
           float* __restrict__ out)
{
    extern __shared__ float smem[];
    float* mem_s  = smem;                     // [ROWS][MPAD]
    float* gsm    = smem + OFF_GSM;           // [8][192]
    float* part   = smem + OFF_PART;          // [3][8][192]
    float* head   = smem + OFF_HEAD;          // [2][2][192]
    float* bias_s = smem + OFF_BIAS;          // [192]
    int*   best_s = (int*)(smem + OFF_BEST);  // [8][64]

    const int tid  = threadIdx.x;
    const int b    = blockIdx.x / TILES_PER_B;
    const int l0   = (blockIdx.x % TILES_PER_B) * TILE;
    const int lend = (l0 + TILE < Ln) ? (l0 + TILE) : Ln;
    const int nc   = (lend - l0) / CH;        // 7 or 4

    // ---- stage memory + bias ----
    for (int i = tid; i < ROWS * (Dn / 4); i += NT) {
        int r = i >> 6, c = i & 63;
        ((float4*)(mem_s + r * MPAD))[c] = ((const float4*)mem)[i];
    }
    if (tid < ROWS) bias_s[tid] = bias[tid];
    __syncthreads();

    // GEMM decomposition: 96 column-pairs x 4 K-chunks (kc warp-uniform: 96 = 3 warps)
    const int cp = tid % 96;
    const int kc = tid / 96;                  // 0..3
    const int j0 = cp, j1 = cp + 96;
    const ulonglong2* mp0 = (const ulonglong2*)(mem_s + j0 * MPAD);
    const ulonglong2* mp1 = (const ulonglong2*)(mem_s + j1 * MPAD);
    float* gdst = (kc == 0) ? gsm : (part + (kc - 1) * (CH * ROWS));
    const int d4b = kc * 16;

    const int rI = tid / ROWS;                // 0/1 (NT == 2*ROWS)
    const int jj = tid - rI * ROWS;

    const float* xb = x + (size_t)b * Ln * Dn;

    // ---- prologue: head[0] (l' = l0-2, l0-1, full-K) + GEMM chunk 0 ----
    {
        int lp = l0 - 2 + rI;
        float v = 0.f;
        if (lp >= 0) {
            const ulonglong2* mp = (const ulonglong2*)(mem_s + jj * MPAD);
            const ulonglong2* xp = (const ulonglong2*)(xb + (size_t)lp * Dn);
            u64 a0 = 0ULL, a1 = 0ULL;
            #pragma unroll 8
            for (int d4 = 0; d4 < 64; ++d4) {
                ulonglong2 m  = mp[d4];
                ulonglong2 xv = xp[d4];
                a0 = fma2(m.x, xv.x, a0);
                a1 = fma2(m.y, xv.y, a1);
            }
            v = hsum2(add2(a0, a1));
        }
        head[rI * ROWS + jj] = v;             // buffer 0
    }
    gemm_chunk(xb, l0, mp0, mp1, gdst, d4b, j0, j1);
    __syncthreads();

    for (int ci = 0; ci < nc; ci++) {
        const int c0  = l0 + ci * CH;
        const int cur = ci & 1;
        float* hc = head + cur * (2 * ROWS);
        float* hn = head + (cur ^ 1) * (2 * ROWS);

        // ======== Phase A: roll + argmax (reads gsm/part/head_cur) ========
        {   // roll: head_next[rI] = combined G row (6+rI) = l' = c0+6+rI
            int row = (6 + rI) * ROWS + jj;
            hn[rI * ROWS + jj] = gsm[row] + part[row]
                               + part[CH * ROWS + row]
                               + part[2 * CH * ROWS + row];
        }
        for (int pm = tid; pm < CH * SLOTS; pm += NT) {
            int p  = pm >> 6;
            int m3 = (pm & 63) * 3;
            float sc[3];
            #pragma unroll
            for (int n = 0; n < 3; n++) {
                int row = p + n - 2;
                int idx = m3 + n;
                float s;
                if (row < 0) {
                    s = hc[(row + 2) * ROWS + idx];
                } else {
                    int o = row * ROWS + idx;
                    s = gsm[o] + part[o] + part[CH * ROWS + o] + part[2 * CH * ROWS + o];
                }
                sc[n] = s + bias_s[idx];
            }
            int   bn = 0;
            float bv = sc[0];
            if (sc[1] > bv) { bv = sc[1]; bn = 1; }
            if (sc[2] > bv) { bv = sc[2]; bn = 2; }
            best_s[pm] = (m3 + bn) * MPAD;
        }
        __syncthreads();

        // ======== Phase B: gather_i (crossbar) || GEMM_{i+1} (FFMA) ========
        for (int it = tid; it < CH * (Dn / 4); it += NT) {
            int p = it >> 6, d4 = it & 63;
            const int4* bp = (const int4*)(best_s + p * SLOTS);
            u64 ax[4] = {0ULL, 0ULL, 0ULL, 0ULL};
            u64 ay[4] = {0ULL, 0ULL, 0ULL, 0ULL};
            #pragma unroll
            for (int m4 = 0; m4 < 16; m4++) {
                int4 r4 = bp[m4];             // warp-uniform broadcast
                int q = m4 & 3;
                ulonglong2 v;
                v = ((const ulonglong2*)(mem_s + r4.x))[d4];
                ax[q] = add2(ax[q], v.x); ay[q] = add2(ay[q], v.y);
                v = ((const ulonglong2*)(mem_s + r4.y))[d4];
                ax[q] = add2(ax[q], v.x); ay[q] = add2(ay[q], v.y);
                v = ((const ulonglong2*)(mem_s + r4.z))[d4];
                ax[q] = add2(ax[q], v.x); ay[q] = add2(ay[q], v.y);
                v = ((const ulonglong2*)(mem_s + r4.w))[d4];
                ax[q] = add2(ax[q], v.x); ay[q] = add2(ay[q], v.y);
            }
            u64 a0 = add2(add2(ax[0], ax[1]), add2(ax[2], ax[3]));
            u64 a1 = add2(add2(ay[0], ay[1]), add2(ay[2], ay[3]));
            float x0, x1, y0, y1;
            asm("mov.b64 {%0,%1}, %2;" : "=f"(x0), "=f"(x1) : "l"(a0));
            asm("mov.b64 {%0,%1}, %2;" : "=f"(y0), "=f"(y1) : "l"(a1));
            ((float4*)(out + ((size_t)b * Ln + c0 + p) * Dn))[d4] =
                make_float4(x0, x1, y0, y1);
        }
        if (ci + 1 < nc)
            gemm_chunk(xb, c0 + CH, mp0, mp1, gdst, d4b, j0, j1);
        __syncthreads();
    }
}

extern "C" void kernel_launch(void* const* d_in, const int* in_sizes, int n_in,
                              void* d_out, int out_size)
{
    const float* x    = (const float*)d_in[0];   // (4, 2048, 256) f32
    const float* mem  = (const float*)d_in[1];   // (64, 3, 256)   f32
    const float* bias = (const float*)d_in[2];   // (64, 3)        f32
    float* out        = (float*)d_out;           // (4, 2048, 256) f32

    (void)in_sizes; (void)n_in; (void)out_size;

    const int smem_bytes = SMEM_WORDS * (int)sizeof(float);   // 230144
    cudaFuncSetAttribute(pnm_kernel,
                         cudaFuncAttributeMaxDynamicSharedMemorySize,
                         smem_bytes);

    pnm_kernel<<<Bn * TILES_PER_B, NT, smem_bytes>>>(x, mem, bias, out);
}

// round 5
// speedup vs baseline: 1.4425x; 1.0570x over previous
#include <cuda_runtime.h>

// Problem constants
#define Bn 4
#define Ln 2048
#define Dn 256
#define SLOTS 64
#define ROWS 192          // SLOTS * 3
#define MPAD 260          // padded stride (words): 8-lane groups cover all 32 banks
#define TILE 56           // 4 * 37 = 148 blocks = one full wave
#define CH 8              // positions per chunk
#define NT 384            // 12 warps
#define TILES_PER_B 37

// smem layout (words)
#define OFF_GSM  (ROWS * MPAD)                // 49920 : gsm[8][192]  K-half 0
#define OFF_PART (OFF_GSM + CH * ROWS)        // +1536 : part[8][192] K-half 1
#define OFF_HEAD (OFF_PART + CH * ROWS)       // +1536 : head[2][2][192] rolled G rows
#define OFF_BIAS (OFF_HEAD + 2 * 2 * ROWS)    // +768
#define OFF_BEST (OFF_BIAS + ROWS)            // +192  : best[8][64] (row*MPAD premult)
#define OFF_XS   (OFF_BEST + CH * SLOTS)      // +512  : xs[8][256] staged x chunk
#define SMEM_WORDS (OFF_XS + CH * Dn)         // +2048 -> 56512 words = 226048 B

typedef unsigned long long u64;

__device__ __forceinline__ u64 fma2(u64 a, u64 b, u64 c) {
    u64 d;
    asm("fma.rn.f32x2 %0, %1, %2, %3;" : "=l"(d) : "l"(a), "l"(b), "l"(c));
    return d;
}
__device__ __forceinline__ u64 add2(u64 a, u64 b) {
    u64 d;
    asm("add.rn.f32x2 %0, %1, %2;" : "=l"(d) : "l"(a), "l"(b));
    return d;
}
__device__ __forceinline__ float hsum2(u64 a) {
    float lo, hi;
    asm("mov.b64 {%0,%1}, %2;" : "=f"(lo), "=f"(hi) : "l"(a));
    return lo + hi;
}

// GEMM slice: 1 column (j), half-K (32 d4), 8 rows. x from smem (broadcast LDS).
__device__ __forceinline__ void gemm_chunk(
    const float* __restrict__ xs,
    const ulonglong2* __restrict__ mp,
    float* __restrict__ gdst, int d4b, int j)
{
    const ulonglong2* xp = (const ulonglong2*)xs;
    u64 acc[8];
    #pragma unroll
    for (int r = 0; r < 8; r++) acc[r] = 0ULL;
    #pragma unroll 8
    for (int d4 = d4b; d4 < d4b + 32; ++d4) {
        ulonglong2 m = mp[d4];                 // 4-phase LDS.128 (bank-perfect)
        #pragma unroll
        for (int r = 0; r < 8; r++) {
            ulonglong2 xv = xp[r * 64 + d4];   // warp-uniform broadcast LDS.128
            acc[r] = fma2(m.x, xv.x, acc[r]);
            acc[r] = fma2(m.y, xv.y, acc[r]);
        }
    }
    #pragma unroll
    for (int r = 0; r < 8; r++) gdst[r * ROWS + j] = hsum2(acc[r]);
}

__global__ void __launch_bounds__(NT, 1)
pnm_kernel(const float* __restrict__ x,
           const float* __restrict__ mem,
           const float* __restrict__ bias,
           float* __restrict__ out)
{
    extern __shared__ float smem[];
    float* mem_s  = smem;                     // [ROWS][MPAD]
    float* gsm    = smem + OFF_GSM;           // [8][192]
    float* part   = smem + OFF_PART;          // [8][192]
    float* head   = smem + OFF_HEAD;          // [2][2][192]
    float* bias_s = smem + OFF_BIAS;          // [192]
    int*   best_s = (int*)(smem + OFF_BEST);  // [8][64]
    float* xs     = smem + OFF_XS;            // [8][256]

    const int tid  = threadIdx.x;
    const int b    = blockIdx.x / TILES_PER_B;
    const int l0   = (blockIdx.x % TILES_PER_B) * TILE;
    const int lend = (l0 + TILE < Ln) ? (l0 + TILE) : Ln;
    const int nc   = (lend - l0) / CH;        // 7 or 4

    const float* xb = x + (size_t)b * Ln * Dn;

    // ---- stage memory + bias + x chunk 0 ----
    for (int i = tid; i < ROWS * (Dn / 4); i += NT) {
        int r = i >> 6, c = i & 63;
        ((float4*)(mem_s + r * MPAD))[c] = ((const float4*)mem)[i];
    }
    if (tid < ROWS) bias_s[tid] = bias[tid];
    for (int i = tid; i < CH * (Dn / 4); i += NT) {
        int r = i >> 6, c = i & 63;
        ((float4*)(xs + r * Dn))[c] =
            ((const float4*)(xb + (size_t)(l0 + r) * Dn))[c];
    }
    __syncthreads();

    // GEMM decomposition: 192 columns x 2 K-halves (kc warp-uniform: 192 = 6 warps)
    const int jc = tid % ROWS;                // column (mem row)
    const int kc = tid / ROWS;                // 0/1 -> d4 in [kc*32, kc*32+32)
    const ulonglong2* mp = (const ulonglong2*)(mem_s + jc * MPAD);
    float* gdst = (kc == 0) ? gsm : part;
    const int d4b = kc * 32;

    const int rI = tid / ROWS;                // reuse 0/1 split for head work
    const int jj = jc;

    // ---- prologue: head[0] (l' = l0-2, l0-1, full-K) + GEMM chunk 0 ----
    {
        int lp = l0 - 2 + rI;
        float v = 0.f;
        if (lp >= 0) {
            const ulonglong2* mpr = (const ulonglong2*)(mem_s + jj * MPAD);
            const ulonglong2* xp  = (const ulonglong2*)(xb + (size_t)lp * Dn);
            u64 a0 = 0ULL, a1 = 0ULL;
            #pragma unroll 8
            for (int d4 = 0; d4 < 64; ++d4) {
                ulonglong2 m  = mpr[d4];
                ulonglong2 xv = xp[d4];
                a0 = fma2(m.x, xv.x, a0);
                a1 = fma2(m.y, xv.y, a1);
            }
            v = hsum2(add2(a0, a1));
        }
        head[rI * ROWS + jj] = v;             // buffer 0
    }
    gemm_chunk(xs, mp, gdst, d4b, jc);
    __syncthreads();

    for (int ci = 0; ci < nc; ci++) {
        const int c0  = l0 + ci * CH;
        const int cur = ci & 1;
        float* hc = head + cur * (2 * ROWS);
        float* hn = head + (cur ^ 1) * (2 * ROWS);

        // ===== Phase A: stage xs_{i+1} + roll + argmax =====
        if (ci + 1 < nc) {
            for (int i = tid; i < CH * (Dn / 4); i += NT) {
                int r = i >> 6, c = i & 63;
                ((float4*)(xs + r * Dn))[c] =
                    ((const float4*)(xb + (size_t)(c0 + CH + r) * Dn))[c];
            }
        }
        {   // roll: head_next[rI] = G row (6+rI) = l' = c0+6+rI
            int row = (6 + rI) * ROWS + jj;
            hn[rI * ROWS + jj] = gsm[row] + part[row];
        }
        for (int pm = tid; pm < CH * SLOTS; pm += NT) {
            int p  = pm >> 6;
            int m3 = (pm & 63) * 3;
            float sc[3];
            #pragma unroll
            for (int n = 0; n < 3; n++) {
                int row = p + n - 2;
                int idx = m3 + n;
                float s;
                if (row < 0) {
                    s = hc[(row + 2) * ROWS + idx];
                } else {
                    int o = row * ROWS + idx;
                    s = gsm[o] + part[o];
                }
                sc[n] = s + bias_s[idx];
            }
            int   bn = 0;
            float bv = sc[0];
            if (sc[1] > bv) { bv = sc[1]; bn = 1; }
            if (sc[2] > bv) { bv = sc[2]; bn = 2; }
            best_s[pm] = (m3 + bn) * MPAD;
        }
        __syncthreads();

        // ===== Phase B: gather_i (crossbar) || GEMM_{i+1} (FFMA) =====
        for (int it = tid; it < CH * (Dn / 4); it += NT) {
            int p = it >> 6, d4 = it & 63;
            const int4* bp = (const int4*)(best_s + p * SLOTS);
            u64 ax[4] = {0ULL, 0ULL, 0ULL, 0ULL};
            u64 ay[4] = {0ULL, 0ULL, 0ULL, 0ULL};
            #pragma unroll
            for (int m4 = 0; m4 < 16; m4++) {
                int4 r4 = bp[m4];             // warp-uniform broadcast
                int q = m4 & 3;
                ulonglong2 v;
                v = ((const ulonglong2*)(mem_s + r4.x))[d4];
                ax[q] = add2(ax[q], v.x); ay[q] = add2(ay[q], v.y);
                v = ((const ulonglong2*)(mem_s + r4.y))[d4];
                ax[q] = add2(ax[q], v.x); ay[q] = add2(ay[q], v.y);
                v = ((const ulonglong2*)(mem_s + r4.z))[d4];
                ax[q] = add2(ax[q], v.x); ay[q] = add2(ay[q], v.y);
                v = ((const ulonglong2*)(mem_s + r4.w))[d4];
                ax[q] = add2(ax[q], v.x); ay[q] = add2(ay[q], v.y);
            }
            u64 a0 = add2(add2(ax[0], ax[1]), add2(ax[2], ax[3]));
            u64 a1 = add2(add2(ay[0], ay[1]), add2(ay[2], ay[3]));
            float x0, x1, y0, y1;
            asm("mov.b64 {%0,%1}, %2;" : "=f"(x0), "=f"(x1) : "l"(a0));
            asm("mov.b64 {%0,%1}, %2;" : "=f"(y0), "=f"(y1) : "l"(a1));
            ((float4*)(out + ((size_t)b * Ln + c0 + p) * Dn))[d4] =
                make_float4(x0, x1, y0, y1);
        }
        if (ci + 1 < nc)
            gemm_chunk(xs, mp, gdst, d4b, jc);
        __syncthreads();
    }
}

extern "C" void kernel_launch(void* const* d_in, const int* in_sizes, int n_in,
                              void* d_out, int out_size)
{
    const float* x    = (const float*)d_in[0];   // (4, 2048, 256) f32
    const float* mem  = (const float*)d_in[1];   // (64, 3, 256)   f32
    const float* bias = (const float*)d_in[2];   // (64, 3)        f32
    float* out        = (float*)d_out;           // (4, 2048, 256) f32

    (void)in_sizes; (void)n_in; (void)out_size;

    const int smem_bytes = SMEM_WORDS * (int)sizeof(float);   // 226048
    cudaFuncSetAttribute(pnm_kernel,
                         cudaFuncAttributeMaxDynamicSharedMemorySize,
                         smem_bytes);

    pnm_kernel<<<Bn * TILES_PER_B, NT, smem_bytes>>>(x, mem, bias, out);
}

// round 6
// speedup vs baseline: 1.6341x; 1.1328x over previous
#include <cuda_runtime.h>

// Problem constants
#define Bn 4
#define Ln 2048
#define Dn 256
#define SLOTS 64
#define ROWS 192          // SLOTS * 3
#define MPAD 260          // padded stride (words): bank-stride 4 -> conflict-free LDS.128
#define TILE 56           // 4 * 37 = 148 blocks = one full wave
#define CH 8              // positions per chunk
#define NT 512            // 16 warps
#define TILES_PER_B 37

// smem layout (words) — unchanged from R5 (226048 B)
#define OFF_GSM  (ROWS * MPAD)                // 49920 : gsm[8][192]  K-half 0
#define OFF_PART (OFF_GSM + CH * ROWS)        // +1536 : part[8][192] K-half 1
#define OFF_HEAD (OFF_PART + CH * ROWS)       // +1536 : head[2][2][192]
#define OFF_BIAS (OFF_HEAD + 2 * 2 * ROWS)    // +768
#define OFF_BEST (OFF_BIAS + ROWS)            // +192  : best[8][64] (row*MPAD premult)
#define OFF_XS   (OFF_BEST + CH * SLOTS)      // +512  : xs[8][256]
#define SMEM_WORDS (OFF_XS + CH * Dn)         // +2048 -> 56512 words = 226048 B

typedef unsigned long long u64;

__device__ __forceinline__ u64 fma2(u64 a, u64 b, u64 c) {
    u64 d;
    asm("fma.rn.f32x2 %0, %1, %2, %3;" : "=l"(d) : "l"(a), "l"(b), "l"(c));
    return d;
}
__device__ __forceinline__ u64 add2(u64 a, u64 b) {
    u64 d;
    asm("add.rn.f32x2 %0, %1, %2;" : "=l"(d) : "l"(a), "l"(b));
    return d;
}
__device__ __forceinline__ float hsum2(u64 a) {
    float lo, hi;
    asm("mov.b64 {%0,%1}, %2;" : "=f"(lo), "=f"(hi) : "l"(a));
    return lo + hi;
}

// GEMM slice: 2 columns (j0, j0+96), half-K (32 d4), 8 rows. x via broadcast LDS.
__device__ __forceinline__ void gemm_chunk(
    const float* __restrict__ xs,
    const ulonglong2* __restrict__ mp0,
    const ulonglong2* __restrict__ mp1,
    float* __restrict__ gdst, int d4b, int j0)
{
    const ulonglong2* xp = (const ulonglong2*)xs;
    u64 a0[8], a1[8];
    #pragma unroll
    for (int r = 0; r < 8; r++) { a0[r] = 0ULL; a1[r] = 0ULL; }
    #pragma unroll 4
    for (int d4 = d4b; d4 < d4b + 32; ++d4) {
        ulonglong2 m0 = mp0[d4];               // 4-phase LDS.128 (bank-perfect)
        ulonglong2 m1 = mp1[d4];
        #pragma unroll
        for (int r = 0; r < 8; r++) {
            ulonglong2 xv = xp[r * 64 + d4];   // warp-uniform broadcast LDS.128
            a0[r] = fma2(m0.x, xv.x, a0[r]);
            a0[r] = fma2(m0.y, xv.y, a0[r]);
            a1[r] = fma2(m1.x, xv.x, a1[r]);
            a1[r] = fma2(m1.y, xv.y, a1[r]);
        }
    }
    #pragma unroll
    for (int r = 0; r < 8; r++) {
        gdst[r * ROWS + j0]      = hsum2(a0[r]);
        gdst[r * ROWS + j0 + 96] = hsum2(a1[r]);
    }
}

__device__ __forceinline__ void gather_one(
    const float* __restrict__ mem_s, const int* __restrict__ best_s,
    float* __restrict__ out, size_t orow, int it)
{
    int p = it >> 6, d4 = it & 63;
    const int4* bp = (const int4*)(best_s + p * SLOTS);
    u64 ax[4] = {0ULL, 0ULL, 0ULL, 0ULL};
    u64 ay[4] = {0ULL, 0ULL, 0ULL, 0ULL};
    #pragma unroll
    for (int m4 = 0; m4 < 16; m4++) {
        int4 r4 = bp[m4];                      // warp-uniform broadcast
        int q = m4 & 3;
        ulonglong2 v;
        v = ((const ulonglong2*)(mem_s + r4.x))[d4];
        ax[q] = add2(ax[q], v.x); ay[q] = add2(ay[q], v.y);
        v = ((const ulonglong2*)(mem_s + r4.y))[d4];
        ax[q] = add2(ax[q], v.x); ay[q] = add2(ay[q], v.y);
        v = ((const ulonglong2*)(mem_s + r4.z))[d4];
        ax[q] = add2(ax[q], v.x); ay[q] = add2(ay[q], v.y);
        v = ((const ulonglong2*)(mem_s + r4.w))[d4];
        ax[q] = add2(ax[q], v.x); ay[q] = add2(ay[q], v.y);
    }
    u64 s0 = add2(add2(ax[0], ax[1]), add2(ax[2], ax[3]));
    u64 s1 = add2(add2(ay[0], ay[1]), add2(ay[2], ay[3]));
    float x0, x1, y0, y1;
    asm("mov.b64 {%0,%1}, %2;" : "=f"(x0), "=f"(x1) : "l"(s0));
    asm("mov.b64 {%0,%1}, %2;" : "=f"(y0), "=f"(y1) : "l"(s1));
    ((float4*)(out + (orow + p) * Dn))[d4] = make_float4(x0, x1, y0, y1);
}

__global__ void __launch_bounds__(NT, 1)
pnm_kernel(const float* __restrict__ x,
           const float* __restrict__ mem,
           const float* __restrict__ bias,
           float* __restrict__ out)
{
    extern __shared__ float smem[];
    float* mem_s  = smem;                     // [ROWS][MPAD]
    float* gsm    = smem + OFF_GSM;           // [8][192]
    float* part   = smem + OFF_PART;          // [8][192]
    float* head   = smem + OFF_HEAD;          // [2][2][192]
    float* bias_s = smem + OFF_BIAS;          // [192]
    int*   best_s = (int*)(smem + OFF_BEST);  // [8][64]
    float* xs     = smem + OFF_XS;            // [8][256]

    const int tid  = threadIdx.x;
    const int b    = blockIdx.x / TILES_PER_B;
    const int l0   = (blockIdx.x % TILES_PER_B) * TILE;
    const int lend = (l0 + TILE < Ln) ? (l0 + TILE) : Ln;
    const int nc   = (lend - l0) / CH;        // 7 or 4

    const float* xb = x + (size_t)b * Ln * Dn;
    const size_t orow0 = (size_t)b * Ln;

    // ---- stage memory + bias + x chunk 0 ----
    for (int i = tid; i < ROWS * (Dn / 4); i += NT) {
        int r = i >> 6, c = i & 63;
        ((float4*)(mem_s + r * MPAD))[c] = ((const float4*)mem)[i];
    }
    if (tid < ROWS) bias_s[tid] = bias[tid];
    for (int i = tid; i < CH * (Dn / 4); i += NT) {
        int r = i >> 6, c = i & 63;
        ((float4*)(xs + r * Dn))[c] =
            ((const float4*)(xb + (size_t)(l0 + r) * Dn))[c];
    }
    __syncthreads();

    // GEMM: 192 threads (6 warps) = 96 col-pairs x 2 K-halves (kc warp-uniform)
    const bool is_gemm = (tid < 192);
    const int  q  = tid % 96;                 // col pair: j0=q, j1=q+96
    const int  kc = (tid / 96) & 1;           // 0/1 (valid for tid<192)
    const ulonglong2* mp0 = (const ulonglong2*)(mem_s + q * MPAD);
    const ulonglong2* mp1 = (const ulonglong2*)(mem_s + (q + 96) * MPAD);
    float* gdst = (kc == 0) ? gsm : part;
    const int d4b = kc * 32;

    // head-roll mapping (384 threads)
    const int rI = tid / ROWS;                // 0/1 for tid<384
    const int jj = tid % ROWS;

    // ---- prologue: head[0] (l' = l0-2, l0-1, full-K) + GEMM chunk 0 ----
    if (tid < 2 * ROWS) {
        int lp = l0 - 2 + rI;
        float v = 0.f;
        if (lp >= 0) {
            const ulonglong2* mpr = (const ulonglong2*)(mem_s + jj * MPAD);
            const ulonglong2* xp  = (const ulonglong2*)(xb + (size_t)lp * Dn);
            u64 p0 = 0ULL, p1 = 0ULL;
            #pragma unroll 8
            for (int d4 = 0; d4 < 64; ++d4) {
                ulonglong2 m  = mpr[d4];
                ulonglong2 xv = xp[d4];
                p0 = fma2(m.x, xv.x, p0);
                p1 = fma2(m.y, xv.y, p1);
            }
            v = hsum2(add2(p0, p1));
        }
        head[rI * ROWS + jj] = v;             // buffer 0
    }
    if (is_gemm) gemm_chunk(xs, mp0, mp1, gdst, d4b, q);
    __syncthreads();

    for (int ci = 0; ci < nc; ci++) {
        const int c0  = l0 + ci * CH;
        const int cur = ci & 1;
        float* hc = head + cur * (2 * ROWS);
        float* hn = head + (cur ^ 1) * (2 * ROWS);

        // ===== Phase A: stage xs_{i+1} + roll + argmax =====
        if (ci + 1 < nc) {
            for (int i = tid; i < CH * (Dn / 4); i += NT) {
                int r = i >> 6, c = i & 63;
                ((float4*)(xs + r * Dn))[c] =
                    ((const float4*)(xb + (size_t)(c0 + CH + r) * Dn))[c];
            }
        }
        if (tid < 2 * ROWS) {   // roll: head_next[rI] = G row (6+rI) = l' = c0+6+rI
            int row = (6 + rI) * ROWS + jj;
            hn[rI * ROWS + jj] = gsm[row] + part[row];
        }
        {   // argmax: exactly one (p, m) per thread (NT == CH*SLOTS)
            int p  = tid >> 6;
            int m3 = (tid & 63) * 3;
            float sc[3];
            #pragma unroll
            for (int n = 0; n < 3; n++) {
                int row = p + n - 2;
                int idx = m3 + n;
                float s;
                if (row < 0) {
                    s = hc[(row + 2) * ROWS + idx];
                } else {
                    int o = row * ROWS + idx;
                    s = gsm[o] + part[o];
                }
                sc[n] = s + bias_s[idx];
            }
            int   bn = 0;
            float bv = sc[0];
            if (sc[1] > bv) { bv = sc[1]; bn = 1; }
            if (sc[2] > bv) { bv = sc[2]; bn = 2; }
            best_s[tid] = (m3 + bn) * MPAD;
        }
        __syncthreads();

        // ===== Phase B: gather_i (10 warps, crossbar) || GEMM_{i+1} (6 warps, FFMA) =====
        if (!is_gemm) {
            gather_one(mem_s, best_s, out, orow0 + c0, tid - 192);      // items 0..319
            if (tid < 384)
                gather_one(mem_s, best_s, out, orow0 + c0, tid + 128);  // items 320..511
        } else if (ci + 1 < nc) {
            gemm_chunk(xs, mp0, mp1, gdst, d4b, q);
        }
        __syncthreads();
    }
}

extern "C" void kernel_launch(void* const* d_in, const int* in_sizes, int n_in,
                              void* d_out, int out_size)
{
    const float* x    = (const float*)d_in[0];   // (4, 2048, 256) f32
    const float* mem  = (const float*)d_in[1];   // (64, 3, 256)   f32
    const float* bias = (const float*)d_in[2];   // (64, 3)        f32
    float* out        = (float*)d_out;           // (4, 2048, 256) f32

    (void)in_sizes; (void)n_in; (void)out_size;

    const int smem_bytes = SMEM_WORDS * (int)sizeof(float);   // 226048
    cudaFuncSetAttribute(pnm_kernel,
                         cudaFuncAttributeMaxDynamicSharedMemorySize,
                         smem_bytes);

    pnm_kernel<<<Bn * TILES_PER_B, NT, smem_bytes>>>(x, mem, bias, out);
}